// round 1
// baseline (speedup 1.0000x reference)
#include <cuda_runtime.h>
#include <cuda_bf16.h>
#include <cstddef>

#define Bn 2
#define Cc 64
#define Hh 256
#define Ww 256
#define HW (Hh*Ww)

// -------- scratch (static device globals; no runtime alloc allowed) --------
__device__ float g_A[(size_t)Bn*Cc*HW];           // 33.5 MB
__device__ float g_B[(size_t)Bn*Cc*HW];           // 33.5 MB
__device__ float g_BIK[(size_t)Bn*9*Cc*HW];       // 302 MB

// ---------------------------------------------------------------------------
// 1x1 fuse conv: concat(image, guidance) [128ch] -> 64ch, + bias, PReLU(a)
// grid (HW/256, B), block 256. Each thread: 1 pixel, 64 accumulators.
// ---------------------------------------------------------------------------
__global__ void fuse1x1_k(const float* __restrict__ img,
                          const float* __restrict__ gui,
                          const float* __restrict__ w,     // [64][128]
                          const float* __restrict__ bias,  // [64]
                          const float* __restrict__ a_ptr, // [1]
                          float* __restrict__ out)
{
    __shared__ float s_w[64*128];
    const int tid = threadIdx.x;
    const int b = blockIdx.y;
    const int p = blockIdx.x * 256 + tid;

    for (int e = tid; e < 64*128; e += 256) s_w[e] = w[e];
    __syncthreads();

    float acc[64];
#pragma unroll
    for (int j = 0; j < 64; ++j) acc[j] = bias[j];

    const float* i0 = img + (size_t)b*Cc*HW + p;
    const float* i1 = gui + (size_t)b*Cc*HW + p;
#pragma unroll 4
    for (int ci = 0; ci < 64; ++ci) {
        float v = i0[(size_t)ci*HW];
#pragma unroll
        for (int j = 0; j < 64; ++j) acc[j] = fmaf(v, s_w[j*128 + ci], acc[j]);
    }
#pragma unroll 4
    for (int ci = 0; ci < 64; ++ci) {
        float v = i1[(size_t)ci*HW];
#pragma unroll
        for (int j = 0; j < 64; ++j) acc[j] = fmaf(v, s_w[j*128 + 64 + ci], acc[j]);
    }

    const float a = a_ptr[0];
    float* ob = out + (size_t)b*Cc*HW + p;
#pragma unroll
    for (int j = 0; j < 64; ++j) {
        float v = acc[j];
        v = (v >= 0.f) ? v : a*v;
        ob[(size_t)j*HW] = v;
    }
}

// ---------------------------------------------------------------------------
// 3x3 conv, 64->64, pad 1, stride 1, optional PReLU, optional residual add.
// grid (W/32, H/16, B*4); block 256.
// Block computes 32x16 spatial tile x 16 output channels.
// Each thread: 2 pixels (rows lyy and lyy+8) x 16 out-ch = 32 accumulators.
// ---------------------------------------------------------------------------
template<bool PRELU, bool RESID>
__global__ void conv3x3_k(const float* __restrict__ in,
                          const float* __restrict__ w,     // [64][64][3][3]
                          const float* __restrict__ bias,  // [64]
                          const float* __restrict__ a_ptr, // [1] (if PRELU)
                          const float* __restrict__ resid, // (if RESID)
                          float* __restrict__ out)
{
    __shared__ float s_in[18*34];
    __shared__ float s_w[16*9];

    const int tid = threadIdx.x;
    const int x0  = blockIdx.x * 32;
    const int y0  = blockIdx.y * 16;
    const int cog = blockIdx.z & 3;
    const int b   = blockIdx.z >> 2;
    const int lx  = tid & 31;
    const int lyy = tid >> 5;   // 0..7

    float acc[2][16];
#pragma unroll
    for (int j = 0; j < 16; ++j) {
        float bv = bias[cog*16 + j];
        acc[0][j] = bv; acc[1][j] = bv;
    }

    const float* inb = in + (size_t)b*Cc*HW;

    for (int ci = 0; ci < Cc; ++ci) {
        const float* inc = inb + (size_t)ci*HW;
        // stage 18x34 halo tile
        for (int e = tid; e < 612; e += 256) {
            int r  = e / 34;
            int c2 = e - r*34;
            int gy = y0 - 1 + r;
            int gx = x0 - 1 + c2;
            float v = 0.f;
            if ((unsigned)gy < (unsigned)Hh && (unsigned)gx < (unsigned)Ww)
                v = inc[gy*Ww + gx];
            s_in[e] = v;
        }
        // stage 16 x 9 weights for this input channel
        if (tid < 144) {
            int j = tid / 9, t = tid - j*9;
            s_w[tid] = w[((cog*16 + j)*Cc + ci)*9 + t];
        }
        __syncthreads();

        float t0[9], t1[9];
#pragma unroll
        for (int k = 0; k < 9; ++k) {
            int dy = k / 3, dx = k - dy*3;
            t0[k] = s_in[(lyy     + dy)*34 + lx + dx];
            t1[k] = s_in[(lyy + 8 + dy)*34 + lx + dx];
        }
#pragma unroll
        for (int j = 0; j < 16; ++j) {
#pragma unroll
            for (int k = 0; k < 9; ++k) {
                float wv = s_w[j*9 + k];
                acc[0][j] = fmaf(t0[k], wv, acc[0][j]);
                acc[1][j] = fmaf(t1[k], wv, acc[1][j]);
            }
        }
        __syncthreads();
    }

    float a = 0.f;
    if (PRELU) a = a_ptr[0];
#pragma unroll
    for (int p = 0; p < 2; ++p) {
        int y = y0 + lyy + p*8;
        int x = x0 + lx;
#pragma unroll
        for (int j = 0; j < 16; ++j) {
            float v = acc[p][j];
            if (PRELU) v = (v >= 0.f) ? v : a*v;
            size_t oidx = ((size_t)(b*Cc + cog*16 + j)*Hh + y)*Ww + x;
            if (RESID) v += resid[oidx];
            out[oidx] = v;
        }
    }
}

// ---------------------------------------------------------------------------
// kg5 1x1 conv: 64 -> 576, + bias, no activation.
// grid (36 co-chunks, 64 pixel tiles, B); block 256.
// Each thread: 4 pixels x 16 out-ch.
// ---------------------------------------------------------------------------
__global__ void kg5_k(const float* __restrict__ in,    // [B][64][HW]
                      const float* __restrict__ w,     // [576][64]
                      const float* __restrict__ bias,  // [576]
                      float* __restrict__ out)         // [B][576][HW]
{
    __shared__ float s_w[16*64];
    const int tid  = threadIdx.x;
    const int coc  = blockIdx.x;   // 0..35
    const int tile = blockIdx.y;   // 0..63
    const int b    = blockIdx.z;

    for (int e = tid; e < 16*64; e += 256) s_w[e] = w[coc*16*64 + e];
    __syncthreads();

    const int p0 = tile*1024 + tid;
    const float* inb = in + (size_t)b*Cc*HW + p0;

    float acc[4][16];
#pragma unroll
    for (int j = 0; j < 16; ++j) {
        float bv = bias[coc*16 + j];
        acc[0][j] = bv; acc[1][j] = bv; acc[2][j] = bv; acc[3][j] = bv;
    }

#pragma unroll 4
    for (int ci = 0; ci < 64; ++ci) {
        const float* ic = inb + (size_t)ci*HW;
        float v0 = ic[0];
        float v1 = ic[256];
        float v2 = ic[512];
        float v3 = ic[768];
#pragma unroll
        for (int j = 0; j < 16; ++j) {
            float wv = s_w[j*64 + ci];
            acc[0][j] = fmaf(v0, wv, acc[0][j]);
            acc[1][j] = fmaf(v1, wv, acc[1][j]);
            acc[2][j] = fmaf(v2, wv, acc[2][j]);
            acc[3][j] = fmaf(v3, wv, acc[3][j]);
        }
    }

#pragma unroll
    for (int j = 0; j < 16; ++j) {
        float* ob = out + ((size_t)b*576 + coc*16 + j)*HW + p0;
        ob[0]   = acc[0][j];
        ob[256] = acc[1][j];
        ob[512] = acc[2][j];
        ob[768] = acc[3][j];
    }
}

// ---------------------------------------------------------------------------
// dynamic filter (torch "unfold" flat-layout quirk preserved):
// out[b,ci,y,x] = sum_{kk=0..8} bik[b, kk*64+ci, y, x] *
//                 image_pad[b, (kk*64+ci)/9, y + ((kk*64+ci)%9)/3 - 1,
//                                            x + ((kk*64+ci)%9)%3 - 1]
// grid (HW/256, B); block 256.
// ---------------------------------------------------------------------------
__global__ void jbf_k(const float* __restrict__ bik,
                      const float* __restrict__ img,
                      float* __restrict__ out)
{
    const int tid = threadIdx.x;
    const int b = blockIdx.y;
    const int p = blockIdx.x * 256 + tid;
    const int y = p >> 8;
    const int x = p & 255;

    const float* bb = bik + (size_t)b*576*HW + p;
    const float* ib = img + (size_t)b*Cc*HW;
    float* ob = out + (size_t)b*Cc*HW + p;

#pragma unroll 2
    for (int ci = 0; ci < 64; ++ci) {
        float acc = 0.f;
#pragma unroll
        for (int kk = 0; kk < 9; ++kk) {
            int f   = kk*64 + ci;
            int ch  = f / 9;
            int tap = f - ch*9;
            int dy  = tap / 3 - 1;
            int dx  = tap - (tap/3)*3 - 1;
            int yy = y + dy, xx = x + dx;
            float iv = 0.f;
            if ((unsigned)yy < (unsigned)Hh && (unsigned)xx < (unsigned)Ww)
                iv = ib[(size_t)ch*HW + yy*Ww + xx];
            acc = fmaf(bb[(size_t)f*HW], iv, acc);
        }
        ob[(size_t)ci*HW] = acc;
    }
}

// ---------------------------------------------------------------------------
extern "C" void kernel_launch(void* const* d_in, const int* in_sizes, int n_in,
                              void* d_out, int out_size)
{
    const float* image   = (const float*)d_in[0];
    const float* guidance= (const float*)d_in[1];
    const float* tensor_w= (const float*)d_in[2];
    const float* tensor_b= (const float*)d_in[3];
    const float* a_jbf   = (const float*)d_in[4];
    const float* kg_w1   = (const float*)d_in[5];
    const float* kg_b1   = (const float*)d_in[6];
    const float* kg_w2   = (const float*)d_in[7];
    const float* kg_b2   = (const float*)d_in[8];
    const float* kg_w3   = (const float*)d_in[9];
    const float* kg_b3   = (const float*)d_in[10];
    const float* kg_w4   = (const float*)d_in[11];
    const float* kg_b4   = (const float*)d_in[12];
    const float* kg_w5   = (const float*)d_in[13];
    const float* kg_b5   = (const float*)d_in[14];
    const float* a_kg    = (const float*)d_in[15];
    const float* jbf_w1  = (const float*)d_in[16];
    const float* jbf_b1  = (const float*)d_in[17];
    const float* jbf_w2  = (const float*)d_in[18];
    const float* jbf_b2  = (const float*)d_in[19];
    float* out = (float*)d_out;

    float *A, *Bb, *BIK;
    cudaGetSymbolAddress((void**)&A,   g_A);
    cudaGetSymbolAddress((void**)&Bb,  g_B);
    cudaGetSymbolAddress((void**)&BIK, g_BIK);

    dim3 blk(256);
    dim3 g1(HW/256, Bn);
    dim3 g3(Ww/32, Hh/16, Bn*4);

    // t = PReLU(conv1x1(cat(image, guidance)))           -> A
    fuse1x1_k<<<g1, blk>>>(image, guidance, tensor_w, tensor_b, a_jbf, A);
    // kg tower
    conv3x3_k<true,false><<<g3, blk>>>(A,  kg_w1, kg_b1, a_kg, nullptr, Bb);
    conv3x3_k<true,false><<<g3, blk>>>(Bb, kg_w2, kg_b2, a_kg, nullptr, A);
    conv3x3_k<true,false><<<g3, blk>>>(A,  kg_w3, kg_b3, a_kg, nullptr, Bb);
    conv3x3_k<true,false><<<g3, blk>>>(Bb, kg_w4, kg_b4, a_kg, nullptr, A);
    // bi_kernel = conv1x1(y4) 64->576                     -> BIK
    kg5_k<<<dim3(36, 64, Bn), blk>>>(A, kg_w5, kg_b5, BIK);
    // dynamic filter                                      -> Bb (= jbf)
    jbf_k<<<g1, blk>>>(BIK, image, Bb);
    // jbf_conv: 3x3 + PReLU(a_jbf), 3x3, + image residual -> d_out
    conv3x3_k<true,false><<<g3, blk>>>(Bb, jbf_w1, jbf_b1, a_jbf, nullptr, A);
    conv3x3_k<false,true><<<g3, blk>>>(A,  jbf_w2, jbf_b2, nullptr, image, out);
}

// round 2
// speedup vs baseline: 1.6764x; 1.6764x over previous
#include <cuda_runtime.h>
#include <cuda_bf16.h>
#include <cstddef>

#define Bn 2
#define Cc 64
#define Hh 256
#define Ww 256
#define HW (Hh*Ww)

typedef unsigned long long ull;

// -------- scratch (static device globals; no runtime alloc allowed) --------
__device__ float g_A[(size_t)Bn*Cc*HW];           // 33.5 MB
__device__ float g_B[(size_t)Bn*Cc*HW];           // 33.5 MB

// ---------------- packed f32x2 helpers ----------------
__device__ __forceinline__ ull pack2(float lo, float hi) {
    ull r; asm("mov.b64 %0, {%1, %2};" : "=l"(r) : "f"(lo), "f"(hi)); return r;
}
__device__ __forceinline__ void unpack2(ull v, float& lo, float& hi) {
    asm("mov.b64 {%0, %1}, %2;" : "=f"(lo), "=f"(hi) : "l"(v));
}
__device__ __forceinline__ ull ffma2(ull a, ull b, ull c) {
    ull d; asm("fma.rn.f32x2 %0, %1, %2, %3;" : "=l"(d) : "l"(a), "l"(b), "l"(c)); return d;
}
__device__ __forceinline__ ull add2(ull a, ull b) {
    ull d; asm("add.rn.f32x2 %0, %1, %2;" : "=l"(d) : "l"(a), "l"(b)); return d;
}

// ---------------------------------------------------------------------------
// 1x1 fuse conv: concat(image, guidance) [128ch] -> 64ch, + bias, PReLU(a)
// grid (64 tiles, 4 cog, B), block 256. Thread: 4 px, 8 packed j-pairs (16 ch).
// ---------------------------------------------------------------------------
__global__ void __launch_bounds__(256, 2)
fuse1x1_k(const float* __restrict__ img,
          const float* __restrict__ gui,
          const float* __restrict__ w,     // [64][128]
          const float* __restrict__ bias,  // [64]
          const float* __restrict__ a_ptr,
          float* __restrict__ out)
{
    __shared__ ull s_wp[8*128];   // packed (co pair) weights for this cog
    const int tid = threadIdx.x;
    const int tile = blockIdx.x;
    const int cog = blockIdx.y;
    const int b = blockIdx.z;

    for (int e = tid; e < 8*128; e += 256) {
        int jp = e >> 7, ci = e & 127;
        int co0 = cog*16 + 2*jp;
        s_wp[e] = pack2(w[co0*128 + ci], w[(co0+1)*128 + ci]);
    }
    __syncthreads();

    const int p0 = tile*1024 + tid;
    ull acc[8][4];
#pragma unroll
    for (int jp = 0; jp < 8; ++jp) {
        int co0 = cog*16 + 2*jp;
        ull bv = pack2(bias[co0], bias[co0+1]);
#pragma unroll
        for (int q = 0; q < 4; ++q) acc[jp][q] = bv;
    }

    const float* i0 = img + (size_t)b*Cc*HW + p0;
    const float* i1 = gui + (size_t)b*Cc*HW + p0;
#pragma unroll 2
    for (int ci = 0; ci < 64; ++ci) {
        const float* ic = i0 + (size_t)ci*HW;
        ull vp[4];
#pragma unroll
        for (int q = 0; q < 4; ++q) { float v = ic[q*256]; vp[q] = pack2(v, v); }
#pragma unroll
        for (int jp = 0; jp < 8; ++jp) {
            ull wv = s_wp[jp*128 + ci];
#pragma unroll
            for (int q = 0; q < 4; ++q) acc[jp][q] = ffma2(vp[q], wv, acc[jp][q]);
        }
    }
#pragma unroll 2
    for (int ci = 0; ci < 64; ++ci) {
        const float* ic = i1 + (size_t)ci*HW;
        ull vp[4];
#pragma unroll
        for (int q = 0; q < 4; ++q) { float v = ic[q*256]; vp[q] = pack2(v, v); }
#pragma unroll
        for (int jp = 0; jp < 8; ++jp) {
            ull wv = s_wp[jp*128 + 64 + ci];
#pragma unroll
            for (int q = 0; q < 4; ++q) acc[jp][q] = ffma2(vp[q], wv, acc[jp][q]);
        }
    }

    const float a = a_ptr[0];
#pragma unroll
    for (int jp = 0; jp < 8; ++jp) {
        int co0 = cog*16 + 2*jp;
        float* o0 = out + ((size_t)b*Cc + co0)*HW + p0;
        float* o1 = o0 + HW;
#pragma unroll
        for (int q = 0; q < 4; ++q) {
            float lo, hi; unpack2(acc[jp][q], lo, hi);
            lo = (lo >= 0.f) ? lo : a*lo;
            hi = (hi >= 0.f) ? hi : a*hi;
            o0[q*256] = lo;
            o1[q*256] = hi;
        }
    }
}

// ---------------------------------------------------------------------------
// 3x3 conv, 64->64, pad 1, optional PReLU, optional residual.
// grid (W/32, H/16, B*4); block 256. 32x16 tile x 16 out-ch.
// Thread: 2 px (rows lyy, lyy+8) x 8 packed j-pairs. 2 in-ch per barrier.
// ---------------------------------------------------------------------------
template<bool PRELU, bool RESID>
__global__ void __launch_bounds__(256, 2)
conv3x3_k(const float* __restrict__ in,
          const float* __restrict__ w,     // [64][64][3][3]
          const float* __restrict__ bias,
          const float* __restrict__ a_ptr,
          const float* __restrict__ resid,
          float* __restrict__ out)
{
    __shared__ float s_in[2][18*34];
    __shared__ ull   s_wp[2][72];      // 8 j-pairs x 9 taps, packed co-pairs

    const int tid = threadIdx.x;
    const int x0  = blockIdx.x * 32;
    const int y0  = blockIdx.y * 16;
    const int cog = blockIdx.z & 3;
    const int b   = blockIdx.z >> 2;
    const int lx  = tid & 31;
    const int lyy = tid >> 5;   // 0..7

    ull acc_a[8], acc_b[8];
#pragma unroll
    for (int jp = 0; jp < 8; ++jp) {
        int co0 = cog*16 + 2*jp;
        ull bv = pack2(bias[co0], bias[co0+1]);
        acc_a[jp] = bv; acc_b[jp] = bv;
    }

    const float* inb = in + (size_t)b*Cc*HW;

    for (int cb = 0; cb < Cc; cb += 2) {
        // stage two input-channel halo tiles
#pragma unroll
        for (int e0 = 0; e0 < 1280; e0 += 256) {
            int e = e0 + tid;
            if (e < 1224) {
                int cc  = e >= 612;
                int idx = e - cc*612;
                int r   = idx / 34;
                int c2  = idx - r*34;
                int gy = y0 - 1 + r;
                int gx = x0 - 1 + c2;
                float v = 0.f;
                if ((unsigned)gy < (unsigned)Hh && (unsigned)gx < (unsigned)Ww)
                    v = inb[(size_t)(cb + cc)*HW + gy*Ww + gx];
                s_in[cc][idx] = v;
            }
        }
        // stage packed weights: 2 channels x 72 pairs
        if (tid < 144) {
            int cc = tid / 72;
            int r  = tid - cc*72;
            int jp = r / 9, k = r - jp*9;
            int co0 = cog*16 + 2*jp;
            int ci  = cb + cc;
            s_wp[cc][r] = pack2(w[(co0*Cc + ci)*9 + k], w[((co0+1)*Cc + ci)*9 + k]);
        }
        __syncthreads();

#pragma unroll
        for (int cc = 0; cc < 2; ++cc) {
            ull tpa[9], tpb[9];
#pragma unroll
            for (int k = 0; k < 9; ++k) {
                int dy = k / 3, dx = k - (k/3)*3;
                float ta = s_in[cc][(lyy     + dy)*34 + lx + dx];
                float tb = s_in[cc][(lyy + 8 + dy)*34 + lx + dx];
                tpa[k] = pack2(ta, ta);
                tpb[k] = pack2(tb, tb);
            }
#pragma unroll
            for (int jp = 0; jp < 8; ++jp) {
#pragma unroll
                for (int k = 0; k < 9; ++k) {
                    ull wv = s_wp[cc][jp*9 + k];
                    acc_a[jp] = ffma2(tpa[k], wv, acc_a[jp]);
                    acc_b[jp] = ffma2(tpb[k], wv, acc_b[jp]);
                }
            }
        }
        __syncthreads();
    }

    float a = 0.f;
    if (PRELU) a = a_ptr[0];
    const int y_a = y0 + lyy, y_b = y_a + 8;
    const int x   = x0 + lx;
#pragma unroll
    for (int jp = 0; jp < 8; ++jp) {
        int co0 = cog*16 + 2*jp;
        float v0a, v1a, v0b, v1b;
        unpack2(acc_a[jp], v0a, v1a);
        unpack2(acc_b[jp], v0b, v1b);
        if (PRELU) {
            v0a = (v0a >= 0.f) ? v0a : a*v0a;
            v1a = (v1a >= 0.f) ? v1a : a*v1a;
            v0b = (v0b >= 0.f) ? v0b : a*v0b;
            v1b = (v1b >= 0.f) ? v1b : a*v1b;
        }
        size_t o0a = ((size_t)(b*Cc + co0)*Hh + y_a)*Ww + x;
        size_t o1a = o0a + (size_t)HW;
        size_t o0b = o0a + 8*Ww;
        size_t o1b = o1a + 8*Ww;
        if (RESID) { v0a += resid[o0a]; v1a += resid[o1a]; v0b += resid[o0b]; v1b += resid[o1b]; }
        out[o0a] = v0a; out[o1a] = v1a; out[o0b] = v0b; out[o1b] = v1b;
    }
}

// ---------------------------------------------------------------------------
// FUSED: kg5 1x1 (64->576) + bias + dynamic joint-bilateral filter.
// out[b,ci,y,x] = sum_{kk} bik_f * tap(f),  f = kk*64+ci,
//   bik_f = kg_b5[f] + dot64(w5[f], y4[:,p]),
//   tap(f) = image[b, f/9, y + (f%9)/3 - 1, x + (f%9)%3 - 1] (0 outside).
// grid (HW/256, B); block 256; 1 px/thread; w5 fully staged in 147KB smem.
// ---------------------------------------------------------------------------
__global__ void __launch_bounds__(256, 1)
kgjbf_k(const float* __restrict__ y4,    // [B][64][HW]
        const float* __restrict__ w5,    // [576][64]
        const float* __restrict__ b5,    // [576]
        const float* __restrict__ img,   // [B][64][HW]
        float* __restrict__ out)         // [B][64][HW]
{
    extern __shared__ float smem[];
    float* s_w5 = smem;            // 36864 floats
    float* s_b5 = smem + 36864;    // 576 floats

    const int tid = threadIdx.x;
    const int b = blockIdx.y;
    const int p = blockIdx.x * 256 + tid;
    const int y = p >> 8;
    const int x = p & 255;

    {
        const float4* src = (const float4*)w5;
        float4* dst = (float4*)s_w5;
        for (int e = tid; e < 9216; e += 256) dst[e] = src[e];
        for (int e = tid; e < 576; e += 256) s_b5[e] = b5[e];
    }
    __syncthreads();

    // load y4 pixel, packed over ci pairs
    ull yp[32];
    {
        const float* yb = y4 + (size_t)b*Cc*HW + p;
#pragma unroll
        for (int c2 = 0; c2 < 32; ++c2)
            yp[c2] = pack2(yb[(size_t)(2*c2)*HW], yb[(size_t)(2*c2+1)*HW]);
    }

    const ull* s_w5u = (const ull*)s_w5;
    const float* ib = img + (size_t)b*Cc*HW;
    float* ob = out + (size_t)b*Cc*HW + p;

    for (int ci = 0; ci < 64; ++ci) {
        float acc = 0.f;
#pragma unroll
        for (int kk = 0; kk < 9; ++kk) {
            const int f = kk*64 + ci;
            const ull* wrow = s_w5u + f*32;
            ull p0 = 0ULL, p1 = 0ULL, p2 = 0ULL, p3 = 0ULL;
#pragma unroll
            for (int c2 = 0; c2 < 32; c2 += 4) {
                p0 = ffma2(yp[c2  ], wrow[c2  ], p0);
                p1 = ffma2(yp[c2+1], wrow[c2+1], p1);
                p2 = ffma2(yp[c2+2], wrow[c2+2], p2);
                p3 = ffma2(yp[c2+3], wrow[c2+3], p3);
            }
            p0 = add2(p0, p1); p2 = add2(p2, p3); p0 = add2(p0, p2);
            float lo, hi; unpack2(p0, lo, hi);
            float bik = lo + hi + s_b5[f];

            int ch  = f / 9;
            int tap = f - ch*9;
            int dy  = tap / 3 - 1;
            int dx  = tap - (tap/3)*3 - 1;
            int yy = y + dy, xx = x + dx;
            float iv = 0.f;
            if ((unsigned)yy < (unsigned)Hh && (unsigned)xx < (unsigned)Ww)
                iv = ib[(size_t)ch*HW + yy*Ww + xx];
            acc = fmaf(bik, iv, acc);
        }
        ob[(size_t)ci*HW] = acc;
    }
}

// ---------------------------------------------------------------------------
extern "C" void kernel_launch(void* const* d_in, const int* in_sizes, int n_in,
                              void* d_out, int out_size)
{
    const float* image   = (const float*)d_in[0];
    const float* guidance= (const float*)d_in[1];
    const float* tensor_w= (const float*)d_in[2];
    const float* tensor_b= (const float*)d_in[3];
    const float* a_jbf   = (const float*)d_in[4];
    const float* kg_w1   = (const float*)d_in[5];
    const float* kg_b1   = (const float*)d_in[6];
    const float* kg_w2   = (const float*)d_in[7];
    const float* kg_b2   = (const float*)d_in[8];
    const float* kg_w3   = (const float*)d_in[9];
    const float* kg_b3   = (const float*)d_in[10];
    const float* kg_w4   = (const float*)d_in[11];
    const float* kg_b4   = (const float*)d_in[12];
    const float* kg_w5   = (const float*)d_in[13];
    const float* kg_b5   = (const float*)d_in[14];
    const float* a_kg    = (const float*)d_in[15];
    const float* jbf_w1  = (const float*)d_in[16];
    const float* jbf_b1  = (const float*)d_in[17];
    const float* jbf_w2  = (const float*)d_in[18];
    const float* jbf_b2  = (const float*)d_in[19];
    float* out = (float*)d_out;

    float *A, *Bb;
    cudaGetSymbolAddress((void**)&A,  g_A);
    cudaGetSymbolAddress((void**)&Bb, g_B);

    static bool attr_set = false;
    if (!attr_set) {
        cudaFuncSetAttribute(kgjbf_k, cudaFuncAttributeMaxDynamicSharedMemorySize, 149760);
        attr_set = true;
    }

    dim3 blk(256);
    dim3 gf(64, 4, Bn);
    dim3 g3(Ww/32, Hh/16, Bn*4);
    dim3 gj(HW/256, Bn);

    // t = PReLU(conv1x1(cat(image, guidance)))           -> A
    fuse1x1_k<<<gf, blk>>>(image, guidance, tensor_w, tensor_b, a_jbf, A);
    // kg tower
    conv3x3_k<true,false><<<g3, blk>>>(A,  kg_w1, kg_b1, a_kg, nullptr, Bb);
    conv3x3_k<true,false><<<g3, blk>>>(Bb, kg_w2, kg_b2, a_kg, nullptr, A);
    conv3x3_k<true,false><<<g3, blk>>>(A,  kg_w3, kg_b3, a_kg, nullptr, Bb);
    conv3x3_k<true,false><<<g3, blk>>>(Bb, kg_w4, kg_b4, a_kg, nullptr, A);
    // fused kg5 + dynamic filter                          -> Bb (= jbf)
    kgjbf_k<<<gj, blk, 149760>>>(A, kg_w5, kg_b5, image, Bb);
    // jbf_conv: 3x3 + PReLU(a_jbf), 3x3, + image residual -> d_out
    conv3x3_k<true,false><<<g3, blk>>>(Bb, jbf_w1, jbf_b1, a_jbf, nullptr, A);
    conv3x3_k<false,true><<<g3, blk>>>(A,  jbf_w2, jbf_b2, nullptr, image, out);
}